// round 2
// baseline (speedup 1.0000x reference)
#include <cuda_runtime.h>
#include <cuda_bf16.h>

#define NPTS   8192
#define THREADS 256
#define R       8
#define ITILE   (THREADS * R)       // 2048
#define JTILE   32
#define ITILES  (NPTS / ITILE)      // 4
#define JTILES  (NPTS / JTILE)      // 256
#define NTASKS  (3 * ITILES * JTILES)  // 3072
#define LOG2E_F 1.4426950408889634f

__device__ __forceinline__ float ex2_approx(float x) {
    float r;
    asm("ex2.approx.ftz.f32 %0, %1;" : "=f"(r) : "f"(x));
    return r;
}

// Scratch (no allocations allowed)
__device__ float4 g_bi[NPTS];   // base:   (x, y, a, 0)   i-side
__device__ float4 g_bj[NPTS];   // base:   (u, v, a, 0)   j-side  (u=-2c2*x, v=-2c2*y)
__device__ float4 g_ti[NPTS];   // target i-side
__device__ float4 g_tj[NPTS];   // target j-side
__device__ double g_sum[3];     // Sbb, Stt, Sbt (unnormalized)
__device__ float  g_params[8];  // s0, s1, c2, m, mbx, mby, mtx, mty
__device__ unsigned int g_task; // dynamic task counter

// ---------------------------------------------------------------------------
// Kernel A: scales, sigma, weighted means (double), reset accumulators+counter
// ---------------------------------------------------------------------------
__global__ void k_setup(const float* __restrict__ base,
                        const float* __restrict__ tgt,
                        const float* __restrict__ log_sigma,
                        const float* __restrict__ log_scale) {
    int tid = threadIdx.x;
    float s0 = expf(log_scale[0]);
    float s1 = expf(log_scale[1]);

    double sbx = 0.0, sby = 0.0, stx = 0.0, sty = 0.0;
    for (int i = tid; i < NPTS; i += THREADS) {
        sbx += (double)(base[2 * i]     * s0);
        sby += (double)(base[2 * i + 1] * s1);
        stx += (double)(tgt[2 * i]      * s0);
        sty += (double)(tgt[2 * i + 1]  * s1);
    }

    __shared__ double sd[THREADS];
    __shared__ double means[4];
    double vals[4] = {sbx, sby, stx, sty};
    for (int q = 0; q < 4; q++) {
        sd[tid] = vals[q];
        __syncthreads();
        for (int s = THREADS / 2; s > 0; s >>= 1) {
            if (tid < s) sd[tid] += sd[tid + s];
            __syncthreads();
        }
        if (tid == 0) means[q] = sd[0] / (double)NPTS;
        __syncthreads();
    }

    if (tid == 0) {
        float sigma  = expf(log_sigma[0]);
        float inv2s2 = 1.0f / (2.0f * sigma * sigma);
        float c2 = -inv2s2 * LOG2E_F;   // exp(-d2*inv2s2) = exp2(c2*d2)
        g_params[0] = s0;
        g_params[1] = s1;
        g_params[2] = c2;
        g_params[3] = -2.0f * c2;
        g_params[4] = (float)means[0];
        g_params[5] = (float)means[1];
        g_params[6] = (float)means[2];
        g_params[7] = (float)means[3];
        g_sum[0] = 0.0; g_sum[1] = 0.0; g_sum[2] = 0.0;
        g_task = 0u;
    }
}

// ---------------------------------------------------------------------------
// Kernel B: center + scale points, precompute (x,y,a) and (u,v,a)
// ---------------------------------------------------------------------------
__global__ void k_prep(const float* __restrict__ base,
                       const float* __restrict__ tgt) {
    int i = blockIdx.x * blockDim.x + threadIdx.x;
    float s0 = g_params[0], s1 = g_params[1];
    float c2 = g_params[2], m  = g_params[3];
    if (i < NPTS) {
        float x = base[2 * i]     * s0 - g_params[4];
        float y = base[2 * i + 1] * s1 - g_params[5];
        float a = c2 * fmaf(x, x, y * y);
        g_bi[i] = make_float4(x, y, a, 0.0f);
        g_bj[i] = make_float4(m * x, m * y, a, 0.0f);
    } else if (i < 2 * NPTS) {
        int k = i - NPTS;
        float x = tgt[2 * k]     * s0 - g_params[6];
        float y = tgt[2 * k + 1] * s1 - g_params[7];
        float a = c2 * fmaf(x, x, y * y);
        g_ti[k] = make_float4(x, y, a, 0.0f);
        g_tj[k] = make_float4(m * x, m * y, a, 0.0f);
    }
}

// ---------------------------------------------------------------------------
// Main kernel: 201M pair exponentials, dynamic task queue
//   task -> (type, i-tile, j-tile); type: 0=bb, 1=tt, 2=bt
//   arg = a_i + a_j + x_i*u_j + y_i*v_j = c2 * |p_i - p_j|^2
// ---------------------------------------------------------------------------
__device__ __forceinline__ void block_reduce_add(double v, double* dst,
                                                 double* sred, int tid) {
    sred[tid] = v;
    __syncthreads();
    for (int s = THREADS / 2; s > 0; s >>= 1) {
        if (tid < s) sred[tid] += sred[tid + s];
        __syncthreads();
    }
    if (tid == 0) atomicAdd(dst, sred[0]);
    __syncthreads();
}

__global__ __launch_bounds__(THREADS) void k_main() {
    __shared__ float4 tile[JTILE];
    __shared__ double sred[THREADS];
    __shared__ unsigned int s_task;

    const int tid = threadIdx.x;
    double abb = 0.0, att = 0.0, abt = 0.0;

    while (true) {
        if (tid == 0) s_task = atomicAdd(&g_task, 1u);
        __syncthreads();                 // publish s_task; all readers of old tile done
        unsigned int t = s_task;
        if (t >= NTASKS) break;

        int type = (int)(t % 3u);
        int rem  = (int)(t / 3u);
        int it   = rem % ITILES;
        int jt   = rem / ITILES;

        const float4* Ai = (type == 1) ? g_ti : g_bi;             // bb,bt: base;  tt: target
        const float4* Bj = (type == 0) ? g_bj : g_tj;             // bb: base;  tt,bt: target

        float xi[R], yi[R], ai[R];
        int i0 = it * ITILE + tid;
#pragma unroll
        for (int r = 0; r < R; r++) {
            float4 p = Ai[i0 + r * THREADS];
            xi[r] = p.x; yi[r] = p.y; ai[r] = p.z;
        }

        if (tid < JTILE) tile[tid] = Bj[jt * JTILE + tid];
        __syncthreads();

        float acc[R];
#pragma unroll
        for (int r = 0; r < R; r++) acc[r] = 0.0f;

#pragma unroll 2
        for (int j = 0; j < JTILE; j++) {
            float4 q = tile[j];
#pragma unroll
            for (int r = 0; r < R; r++) {
                float arg = ai[r] + q.z;
                arg = fmaf(yi[r], q.y, arg);
                arg = fmaf(xi[r], q.x, arg);
                acc[r] += ex2_approx(arg);
            }
        }

        float s = ((acc[0] + acc[1]) + (acc[2] + acc[3])) +
                  ((acc[4] + acc[5]) + (acc[6] + acc[7]));
        if      (type == 0) abb += (double)s;
        else if (type == 1) att += (double)s;
        else                abt += (double)s;
    }

    block_reduce_add(abb, &g_sum[0], sred, tid);
    block_reduce_add(att, &g_sum[1], sred, tid);
    block_reduce_add(abt, &g_sum[2], sred, tid);
}

// ---------------------------------------------------------------------------
// Finalize: normalize and combine
// ---------------------------------------------------------------------------
__global__ void k_finalize(float* __restrict__ out) {
    double inv = 1.0 / ((double)NPTS * (double)NPTS);
    out[0] = (float)((g_sum[0] + g_sum[1] - 2.0 * g_sum[2]) * inv);
}

// ---------------------------------------------------------------------------
extern "C" void kernel_launch(void* const* d_in, const int* in_sizes, int n_in,
                              void* d_out, int out_size) {
    const float* base = (const float*)d_in[0];
    const float* tgt  = (const float*)d_in[1];
    const float* lsig = (const float*)d_in[2];
    const float* lsc  = (const float*)d_in[3];

    k_setup<<<1, THREADS>>>(base, tgt, lsig, lsc);
    k_prep<<<(2 * NPTS + THREADS - 1) / THREADS, THREADS>>>(base, tgt);
    k_main<<<592, THREADS>>>();
    k_finalize<<<1, 1>>>((float*)d_out);
}